// round 10
// baseline (speedup 1.0000x reference)
#include <cuda_runtime.h>
#include <cuda_fp16.h>
#include <math.h>
#include <stdint.h>

// ChildSumTreeLSTM, perfect binary heap depth 17. edge_index unused.
// R10 = R9 (376us) + leaf pointwise fused as gemmIT tail (L2 round trip)
//     + level GEMM rebuilt on the gemmIT skeleton: child-h + pair-sums
//       resident, all 4 U-gates streamed per CTA (A traffic 4x -> 1x).

#define DEPTH 17
#define NN 131071
#define LEAF_START 65535
#define H 128
#define DEEP_D 9
#define DEEP_BLOCKS 128

// ------------------------- scratch -------------------------------------------
__device__ float  g_xi[(size_t)NN * H];
__device__ float  g_xf[(size_t)NN * H];
__device__ float  g_xo[(size_t)NN * H];
__device__ float  g_xu[(size_t)NN * H];
__device__ float  g_h [(size_t)NN * H];
__device__ float  g_c [(size_t)NN * H];
__device__ float  g_gi[32768 * H];
__device__ float  g_go[32768 * H];
__device__ float  g_gu[32768 * H];
__device__ float  g_fl[65536 * H];
__device__ __half g_wIT[4 * H * H];   // chunked [k/32][gate][n][k%32]; Wi,Wf,Wo,Wu
__device__ __half g_wLV[4 * H * H];   // chunked [k/32][gate][n][k%32]; Uf,Ui,Uo,Uu
__device__ float  g_bIT[512];
__device__ int    g_bar[16];

// ------------------------- helpers -------------------------------------------
__device__ __forceinline__ void ldsm4(uint32_t* r, uint32_t addr) {
    asm volatile("ldmatrix.sync.aligned.m8n8.x4.shared.b16 {%0,%1,%2,%3}, [%4];"
        : "=r"(r[0]), "=r"(r[1]), "=r"(r[2]), "=r"(r[3]) : "r"(addr));
}
__device__ __forceinline__ void ldsm2(uint32_t* r, uint32_t addr) {
    asm volatile("ldmatrix.sync.aligned.m8n8.x2.shared.b16 {%0,%1}, [%2];"
        : "=r"(r[0]), "=r"(r[1]) : "r"(addr));
}
__device__ __forceinline__ void mma16(float* d, const uint32_t* a,
                                      uint32_t b0, uint32_t b1) {
    asm volatile(
        "mma.sync.aligned.m16n8k16.row.col.f32.f16.f16.f32 "
        "{%0,%1,%2,%3}, {%4,%5,%6,%7}, {%8,%9}, {%0,%1,%2,%3};"
        : "+f"(d[0]), "+f"(d[1]), "+f"(d[2]), "+f"(d[3])
        : "r"(a[0]), "r"(a[1]), "r"(a[2]), "r"(a[3]), "r"(b0), "r"(b1));
}
__device__ __forceinline__ float sigmoidf_(float x) { return 1.f / (1.f + expf(-x)); }
__device__ __forceinline__ void cpa16(void* dst, const void* src) {
    uint32_t d = (uint32_t)__cvta_generic_to_shared(dst);
    asm volatile("cp.async.cg.shared.global [%0], [%1], 16;" :: "r"(d), "l"(src));
}
#define CP_COMMIT() asm volatile("cp.async.commit_group;")
#define CP_WAIT1()  asm volatile("cp.async.wait_group 1;")

#define STW 136   // whole-K stride (halfs); 272B rows -> conflict-free ldmatrix
#define STC 40    // chunk stride (halfs); 80B rows

// ------------------------- prep ----------------------------------------------
__global__ void prep(const float* __restrict__ Wi, const float* __restrict__ Wf,
                     const float* __restrict__ Wo, const float* __restrict__ Wu,
                     const float* __restrict__ Ui, const float* __restrict__ Uo,
                     const float* __restrict__ Uu, const float* __restrict__ Uf,
                     const float* __restrict__ bWi, const float* __restrict__ bWf,
                     const float* __restrict__ bWo, const float* __restrict__ bWu) {
    const int idx = blockIdx.x * blockDim.x + threadIdx.x;
    if (idx >= 4 * H * H) return;
    const int g = idx >> 14, r = idx & 16383;
    const int n = r >> 7, k = r & 127;
    const float* WW[4] = { Wi, Wf, Wo, Wu };
    const float* UU[4] = { Uf, Ui, Uo, Uu };
    const int dst = (k >> 5) * 16384 + g * 4096 + n * 32 + (k & 31);
    g_wIT[dst] = __float2half_rn(WW[g][n * H + k]);
    g_wLV[dst] = __float2half_rn(UU[g][n * H + k]);
    if (idx < 512) {
        const float* bb[4] = { bWi, bWf, bWo, bWu };
        g_bIT[idx] = bb[idx >> 7][idx & 127];
    }
}

__global__ void zero_bar() {
    if (threadIdx.x < 16) g_bar[threadIdx.x] = 0;
}

// ------------------------- merged input transform + leaf pointwise ------------
#define IT_AS   (128 * STW)
#define IT_BS   (128 * STC)
#define IT_SMEM ((IT_AS + 2 * IT_BS) * 2 + 512 * 4)

__global__ __launch_bounds__(256, 2) void gemmIT(const float* __restrict__ x) {
    extern __shared__ __half smh[];
    __half* As    = smh;
    __half* Bs    = smh + IT_AS;
    float*  biasS = (float*)(smh + IT_AS + 2 * IT_BS);

    const int tid  = threadIdx.x;
    const int lane = tid & 31;
    const int warp = tid >> 5;
    const int wm   = warp >> 2;
    const int wn   = warp & 3;
    const int m0   = blockIdx.x * 128;

    auto issueB = [&](int s) {
        const __half* src = g_wIT + (s & 3) * 16384 + (s >> 2) * 4096;
        __half* buf = Bs + (s & 1) * IT_BS;
#pragma unroll
        for (int i = 0; i < 2; i++) {
            const int idx = tid + i * 256;
            const int row = idx >> 2, seg = idx & 3;
            cpa16(buf + row * STC + seg * 8, src + row * 32 + seg * 8);
        }
    };
    issueB(0); CP_COMMIT();
    issueB(1); CP_COMMIT();

    biasS[tid] = g_bIT[tid];
    biasS[tid + 256] = g_bIT[tid + 256];

#pragma unroll
    for (int i = 0; i < 16; i++) {
        const int idx = tid + i * 256;
        const int row = idx >> 5, k4 = (idx & 31) << 2;
        const int gm = m0 + row;
        float4 v = make_float4(0.f, 0.f, 0.f, 0.f);
        if (gm < NN) v = *(const float4*)(x + (size_t)gm * H + k4);
        __half2* dst = (__half2*)(As + row * STW + k4);
        dst[0] = __floats2half2_rn(v.x, v.y);
        dst[1] = __floats2half2_rn(v.z, v.w);
    }

    float acc[4][4][4];
#pragma unroll
    for (int a = 0; a < 4; a++)
#pragma unroll
        for (int b = 0; b < 4; b++)
#pragma unroll
            for (int d = 0; d < 4; d++) acc[a][b][d] = 0.f;

    const bool allLeaf = (m0 >= LEAF_START);

    const uint32_t sAs  = (uint32_t)__cvta_generic_to_shared(As);
    const uint32_t sBsu = (uint32_t)__cvta_generic_to_shared(Bs);
    const uint32_t aLane = (lane & 15) * (STW * 2) + (lane >> 4) * 16;
    const uint32_t bLane = (lane & 7) * (STC * 2) + ((lane & 8) ? 16 : 0);

    for (int s = 0; s < 16; s++) {
        const int g = s >> 2, c = s & 3;
        CP_WAIT1();
        __syncthreads();
        const bool skip = (g == 1) && allLeaf;
        if (!skip) {
            const uint32_t BbBase = sBsu + (s & 1) * (IT_BS * 2);
#pragma unroll
            for (int ks = 0; ks < 2; ks++) {
                const int ka = c * 32 + ks * 16;
                const int kk = ks * 16;
                uint32_t af[4][4];
#pragma unroll
                for (int mb = 0; mb < 4; mb++) {
                    const uint32_t addr = sAs +
                        (wm * 64 + mb * 16) * (STW * 2) + ka * 2 + aLane;
                    ldsm4(af[mb], addr);
                }
#pragma unroll
                for (int nb = 0; nb < 4; nb++) {
                    uint32_t bf[2];
                    const uint32_t addr = BbBase +
                        (wn * 32 + nb * 8) * (STC * 2) + kk * 2 + bLane;
                    ldsm2(bf, addr);
                    mma16(acc[0][nb], af[0], bf[0], bf[1]);
                    mma16(acc[1][nb], af[1], bf[0], bf[1]);
                    mma16(acc[2][nb], af[2], bf[0], bf[1]);
                    mma16(acc[3][nb], af[3], bf[0], bf[1]);
                }
            }
        }
        __syncthreads();
        if (s + 2 < 16) { issueB(s + 2); CP_COMMIT(); }
        else            { CP_COMMIT(); }

        if (c == 3 && !skip) {
            float* out = (g == 0) ? g_xi : (g == 1) ? g_xf : (g == 2) ? g_xo : g_xu;
            const int rowLimit = (g == 1) ? LEAF_START : NN;
#pragma unroll
            for (int mb = 0; mb < 4; mb++)
#pragma unroll
                for (int nb = 0; nb < 4; nb++) {
                    const int r0  = m0 + wm * 64 + mb * 16 + (lane >> 2);
                    const int col = wn * 32 + nb * 8 + (lane & 3) * 2;
                    const float b0 = biasS[g * 128 + col];
                    const float b1 = biasS[g * 128 + col + 1];
                    if (r0 < rowLimit)
                        *(float2*)(out + (size_t)r0 * H + col) =
                            make_float2(acc[mb][nb][0] + b0, acc[mb][nb][1] + b1);
                    if (r0 + 8 < rowLimit)
                        *(float2*)(out + (size_t)(r0 + 8) * H + col) =
                            make_float2(acc[mb][nb][2] + b0, acc[mb][nb][3] + b1);
                    acc[mb][nb][0] = acc[mb][nb][1] = 0.f;
                    acc[mb][nb][2] = acc[mb][nb][3] = 0.f;
                }
        }
    }

    // ---- fused leaf pointwise tail (reads own just-written rows; L2-hot)
    if (m0 + 127 >= LEAF_START) {
        __syncthreads();   // CTA's global gate writes visible to all its threads
#pragma unroll
        for (int i = 0; i < 16; i++) {
            const int e = tid + i * 256;
            const int row = e >> 5;
            const int node = m0 + row;
            if (node >= LEAF_START && node < NN) {
                const size_t off = (size_t)node * 32 + (e & 31);
                const float4 xi = ((const float4*)g_xi)[off];
                const float4 xo = ((const float4*)g_xo)[off];
                const float4 xu = ((const float4*)g_xu)[off];
                float4 c4, h4;
#define LEAFL(X) { const float ii = sigmoidf_(xi.X);                           \
                   const float oo = sigmoidf_(xo.X);                           \
                   const float uu = tanhf(xu.X);                               \
                   c4.X = ii * uu; h4.X = oo * tanhf(c4.X); }
                LEAFL(x) LEAFL(y) LEAFL(z) LEAFL(w)
#undef LEAFL
                ((float4*)g_c)[off] = c4;
                ((float4*)g_h)[off] = h4;
            }
        }
    }
}

// ------------------------- level GEMM (gemmIT clone) --------------------------
// CTA: 128 child rows resident + 64 pair-sum rows. Streams Uf,Ui,Uo,Uu chunked.
// fl for the 128 child rows; gi/go/gu for the 64 parents.
#define LV_AS   (192 * STW)                   // 26112 halfs
#define LV_BS   (128 * STC)
#define LV_SMEM ((LV_AS + 2 * LV_BS) * 2)     // 72704 B

__global__ __launch_bounds__(256, 2) void gemmLV(int cs, int m0half) {
    extern __shared__ __half smh[];
    __half* As = smh;                 // rows 0..127 child h; 128..191 pair sums
    __half* Bs = smh + LV_AS;

    const int tid  = threadIdx.x;
    const int lane = tid & 31;
    const int warp = tid >> 5;
    const int wm   = warp >> 2;
    const int wn   = warp & 3;
    const int m0   = blockIdx.x * 128;          // child-row base within level

    auto issueB = [&](int s) {
        const __half* src = g_wLV + (s & 3) * 16384 + (s >> 2) * 4096;
        __half* buf = Bs + (s & 1) * LV_BS;
#pragma unroll
        for (int i = 0; i < 2; i++) {
            const int idx = tid + i * 256;
            const int row = idx >> 2, seg = idx & 3;
            cpa16(buf + row * STC + seg * 8, src + row * 32 + seg * 8);
        }
    };
    issueB(0); CP_COMMIT();
    issueB(1); CP_COMMIT();

    // child h (fp16) + fp32 pair sums -> fp16
#pragma unroll
    for (int i = 0; i < 8; i++) {
        const int t  = tid + i * 256;           // 2048 tasks: (pair, k4-group)
        const int p  = t >> 5;
        const int k4 = (t & 31) << 2;
        const float4 a0 = *(const float4*)(g_h + (size_t)(cs + m0 + 2 * p) * H + k4);
        const float4 a1 = *(const float4*)(g_h + (size_t)(cs + m0 + 2 * p + 1) * H + k4);
        __half2* d0 = (__half2*)(As + (2 * p) * STW + k4);
        d0[0] = __floats2half2_rn(a0.x, a0.y);
        d0[1] = __floats2half2_rn(a0.z, a0.w);
        __half2* d1 = (__half2*)(As + (2 * p + 1) * STW + k4);
        d1[0] = __floats2half2_rn(a1.x, a1.y);
        d1[1] = __floats2half2_rn(a1.z, a1.w);
        __half2* ds = (__half2*)(As + (128 + p) * STW + k4);
        ds[0] = __floats2half2_rn(a0.x + a1.x, a0.y + a1.y);
        ds[1] = __floats2half2_rn(a0.z + a1.z, a0.w + a1.w);
    }

    float acc[4][4][4];
#pragma unroll
    for (int a = 0; a < 4; a++)
#pragma unroll
        for (int b = 0; b < 4; b++)
#pragma unroll
            for (int d = 0; d < 4; d++) acc[a][b][d] = 0.f;

    const uint32_t sAs  = (uint32_t)__cvta_generic_to_shared(As);
    const uint32_t sBsu = (uint32_t)__cvta_generic_to_shared(Bs);
    const uint32_t aLane = (lane & 15) * (STW * 2) + (lane >> 4) * 16;
    const uint32_t bLane = (lane & 7) * (STC * 2) + ((lane & 8) ? 16 : 0);

    for (int s = 0; s < 16; s++) {
        const int g = s >> 2, c = s & 3;    // g: 0=Uf, 1=Ui, 2=Uo, 3=Uu
        CP_WAIT1();
        __syncthreads();
        const uint32_t BbBase = sBsu + (s & 1) * (LV_BS * 2);
        if (g == 0) {
            // fl: M=128 over child rows
#pragma unroll
            for (int ks = 0; ks < 2; ks++) {
                const int ka = c * 32 + ks * 16;
                const int kk = ks * 16;
                uint32_t af[4][4];
#pragma unroll
                for (int mb = 0; mb < 4; mb++) {
                    const uint32_t addr = sAs +
                        (wm * 64 + mb * 16) * (STW * 2) + ka * 2 + aLane;
                    ldsm4(af[mb], addr);
                }
#pragma unroll
                for (int nb = 0; nb < 4; nb++) {
                    uint32_t bf[2];
                    const uint32_t addr = BbBase +
                        (wn * 32 + nb * 8) * (STC * 2) + kk * 2 + bLane;
                    ldsm2(bf, addr);
                    mma16(acc[0][nb], af[0], bf[0], bf[1]);
                    mma16(acc[1][nb], af[1], bf[0], bf[1]);
                    mma16(acc[2][nb], af[2], bf[0], bf[1]);
                    mma16(acc[3][nb], af[3], bf[0], bf[1]);
                }
            }
        } else {
            // gi/go/gu: M=64 over pair-sum rows (128..191)
#pragma unroll
            for (int ks = 0; ks < 2; ks++) {
                const int ka = c * 32 + ks * 16;
                const int kk = ks * 16;
                uint32_t af[2][4];
#pragma unroll
                for (int mb = 0; mb < 2; mb++) {
                    const uint32_t addr = sAs +
                        (128 + wm * 32 + mb * 16) * (STW * 2) + ka * 2 + aLane;
                    ldsm4(af[mb], addr);
                }
#pragma unroll
                for (int nb = 0; nb < 4; nb++) {
                    uint32_t bf[2];
                    const uint32_t addr = BbBase +
                        (wn * 32 + nb * 8) * (STC * 2) + kk * 2 + bLane;
                    ldsm2(bf, addr);
                    mma16(acc[0][nb], af[0], bf[0], bf[1]);
                    mma16(acc[1][nb], af[1], bf[0], bf[1]);
                }
            }
        }
        __syncthreads();
        if (s + 2 < 16) { issueB(s + 2); CP_COMMIT(); }
        else            { CP_COMMIT(); }

        if (c == 3) {
            if (g == 0) {
#pragma unroll
                for (int mb = 0; mb < 4; mb++)
#pragma unroll
                    for (int nb = 0; nb < 4; nb++) {
                        const int r0  = m0 + wm * 64 + mb * 16 + (lane >> 2);
                        const int col = wn * 32 + nb * 8 + (lane & 3) * 2;
                        *(float2*)(g_fl + (size_t)r0 * H + col) =
                            make_float2(acc[mb][nb][0], acc[mb][nb][1]);
                        *(float2*)(g_fl + (size_t)(r0 + 8) * H + col) =
                            make_float2(acc[mb][nb][2], acc[mb][nb][3]);
                        acc[mb][nb][0] = acc[mb][nb][1] = 0.f;
                        acc[mb][nb][2] = acc[mb][nb][3] = 0.f;
                    }
            } else {
                float* out = (g == 1) ? g_gi : (g == 2) ? g_go : g_gu;
#pragma unroll
                for (int mb = 0; mb < 2; mb++)
#pragma unroll
                    for (int nb = 0; nb < 4; nb++) {
                        const int r0  = (m0 >> 1) + wm * 32 + mb * 16 + (lane >> 2);
                        const int col = wn * 32 + nb * 8 + (lane & 3) * 2;
                        *(float2*)(out + (size_t)r0 * H + col) =
                            make_float2(acc[mb][nb][0], acc[mb][nb][1]);
                        *(float2*)(out + (size_t)(r0 + 8) * H + col) =
                            make_float2(acc[mb][nb][2], acc[mb][nb][3]);
                        acc[mb][nb][0] = acc[mb][nb][1] = 0.f;
                        acc[mb][nb][2] = acc[mb][nb][3] = 0.f;
                    }
            }
        }
    }
    (void)m0half;
}

// ------------------------- node pointwise -------------------------------------
__global__ void node_pw4(int s, int cnt,
                         const float* __restrict__ bUi, const float* __restrict__ bUo,
                         const float* __restrict__ bUu, const float* __restrict__ bUf) {
    int idx = blockIdx.x * blockDim.x + threadIdx.x;
    if (idx >= cnt * 32) return;
    const int m = idx >> 5;
    const int q = idx & 31;
    const int off  = (s + m) * 32 + q;
    const int cl   = (2 * s + 1 + 2 * m) * 32 + q;
    const int cr   = cl + 32;

    const float4 xi = ((const float4*)g_xi)[off];
    const float4 xf = ((const float4*)g_xf)[off];
    const float4 xo = ((const float4*)g_xo)[off];
    const float4 xu = ((const float4*)g_xu)[off];
    const float4 gi = ((const float4*)g_gi)[idx];
    const float4 go = ((const float4*)g_go)[idx];
    const float4 gu = ((const float4*)g_gu)[idx];
    const float4 fl = ((const float4*)g_fl)[(2 * m) * 32 + q];
    const float4 fr = ((const float4*)g_fl)[(2 * m + 1) * 32 + q];
    const float4 ccl = ((const float4*)g_c)[cl];
    const float4 ccr = ((const float4*)g_c)[cr];
    const float4 bi = ((const float4*)bUi)[q];
    const float4 bo = ((const float4*)bUo)[q];
    const float4 bu = ((const float4*)bUu)[q];
    const float4 bf = ((const float4*)bUf)[q];

    float4 c, h;
#define LANE(X)                                                              \
    {                                                                        \
        const float i  = sigmoidf_(xi.X + gi.X + bi.X);                      \
        const float o  = sigmoidf_(xo.X + go.X + bo.X);                      \
        const float u  = tanhf(xu.X + gu.X + bu.X);                          \
        const float lf = xf.X + bf.X;                                        \
        const float f0 = sigmoidf_(lf + fl.X);                               \
        const float f1 = sigmoidf_(lf + fr.X);                               \
        c.X = i * u + f0 * ccl.X + f1 * ccr.X;                               \
        h.X = o * tanhf(c.X);                                                \
    }
    LANE(x) LANE(y) LANE(z) LANE(w)
#undef LANE
    ((float4*)g_c)[off] = c;
    ((float4*)g_h)[off] = h;
}

// ------------------------- persistent deep levels ----------------------------
#define DEEP_SMEM ((16384 + 2048) * 4)

__global__ __launch_bounds__(256, 1) void deep_levels(
        const float* __restrict__ Ui, const float* __restrict__ Uo,
        const float* __restrict__ Uu, const float* __restrict__ Uf,
        const float* __restrict__ bUi, const float* __restrict__ bUo,
        const float* __restrict__ bUu, const float* __restrict__ bUf) {
    extern __shared__ float sd[];
    float* ws  = sd;
    float* hsm = sd + 16384;

    const int tid  = threadIdx.x;
    const int j    = tid & 31;
    const int ml   = tid >> 5;
    const int jgrp = blockIdx.x & 3;
    const int grp  = blockIdx.x >> 2;
    const int jj   = jgrp * 32 + j;

    const float* U[4] = { Ui, Uo, Uu, Uf };
#pragma unroll
    for (int g = 0; g < 4; g++)
        for (int kq = ml; kq < 32; kq += 8) {
            const float4 v = *(const float4*)(U[g] + jj * H + kq * 4);
            *(float4*)(ws + g * 4096 + kq * 128 + j * 4) = v;
        }

    const float bi_ = bUi[jj], bo_ = bUo[jj], bu_ = bUu[jj], bf_ = bUf[jj];
    const float4* w4 = (const float4*)ws;
    const float4* h4 = (const float4*)hsm;
    __syncthreads();

    for (int d = DEEP_D; d >= 0; --d) {
        const int cnt = 1 << d;
        const int s   = cnt - 1;
        const int cs  = 2 * cnt - 1;
        const int chunk  = (cnt + 31) >> 5;
        const int mstart = grp * chunk;
        const int mend   = (mstart + chunk < cnt) ? mstart + chunk : cnt;

        for (int mb = mstart; mb < mend; mb += 8) {
            const int mcount = (mend - mb < 8) ? (mend - mb) : 8;
            for (int t = tid; t < 2 * mcount * 32; t += 256) {
                const int r = t >> 5, k4 = t & 31;
                ((float4*)hsm)[r * 32 + k4] =
                    *(const float4*)(g_h + (size_t)(cs + 2 * mb + r) * H + k4 * 4);
            }
            __syncthreads();

            if (ml < mcount) {
                const int m = mb + ml;
                float4 ai = make_float4(0.f,0.f,0.f,0.f), ao = ai, au = ai,
                       afl = ai, afr = ai;
#pragma unroll
                for (int kq = 0; kq < 32; kq++) {
                    const float4 hl = h4[(2 * ml)     * 32 + kq];
                    const float4 hr = h4[(2 * ml + 1) * 32 + kq];
                    const float4 wi = w4[kq * 32 + j];
                    const float4 wo = w4[1024 + kq * 32 + j];
                    const float4 wu = w4[2048 + kq * 32 + j];
                    const float4 wf = w4[3072 + kq * 32 + j];
                    const float4 hs = make_float4(hl.x + hr.x, hl.y + hr.y,
                                                  hl.z + hr.z, hl.w + hr.w);
                    ai.x += hs.x * wi.x; ai.y += hs.y * wi.y;
                    ai.z += hs.z * wi.z; ai.w += hs.w * wi.w;
                    ao.x += hs.x * wo.x; ao.y += hs.y * wo.y;
                    ao.z += hs.z * wo.z; ao.w += hs.w * wo.w;
                    au.x += hs.x * wu.x; au.y += hs.y * wu.y;
                    au.z += hs.z * wu.z; au.w += hs.w * wu.w;
                    afl.x += hl.x * wf.x; afl.y += hl.y * wf.y;
                    afl.z += hl.z * wf.z; afl.w += hl.w * wf.w;
                    afr.x += hr.x * wf.x; afr.y += hr.y * wf.y;
                    afr.z += hr.z * wf.z; afr.w += hr.w * wf.w;
                }
                const float ri  = (ai.x + ai.y) + (ai.z + ai.w);
                const float ro  = (ao.x + ao.y) + (ao.z + ao.w);
                const float ru  = (au.x + au.y) + (au.z + au.w);
                const float rfl = (afl.x + afl.y) + (afl.z + afl.w);
                const float rfr = (afr.x + afr.y) + (afr.z + afr.w);

                const size_t off = (size_t)(s + m) * H + jj;
                const float ii = sigmoidf_(g_xi[off] + ri + bi_);
                const float oo = sigmoidf_(g_xo[off] + ro + bo_);
                const float uu = tanhf    (g_xu[off] + ru + bu_);
                const float lf = g_xf[off] + bf_;
                const float f0 = sigmoidf_(lf + rfl);
                const float f1 = sigmoidf_(lf + rfr);
                const float cc = ii * uu
                               + f0 * g_c[(size_t)(cs + 2 * m) * H + jj]
                               + f1 * g_c[(size_t)(cs + 2 * m + 1) * H + jj];
                g_c[off] = cc;
                g_h[off] = oo * tanhf(cc);
            }
            __syncthreads();
        }

        if (d > 0) {
            const int bi = DEEP_D - d;
            __syncthreads();
            if (tid == 0) {
                __threadfence();
                atomicAdd(&g_bar[bi], 1);
                while (((volatile int*)g_bar)[bi] < DEEP_BLOCKS)
                    __nanosleep(64);
            }
            __syncthreads();
            __threadfence();
        }
    }
}

// ------------------------- final projection ----------------------------------
__global__ void final_proj(const float* __restrict__ Wp, const float* __restrict__ bWp,
                           float* __restrict__ out) {
    __shared__ float hs[H];
    const int j = threadIdx.x;
    hs[j] = g_h[j];
    __syncthreads();
    float acc = bWp[j];
#pragma unroll 8
    for (int k = 0; k < H; k++) acc += Wp[j * H + k] * hs[k];
    out[j] = acc;
}

// ------------------------- launch -------------------------------------------
extern "C" void kernel_launch(void* const* d_in, const int* in_sizes, int n_in,
                              void* d_out, int out_size) {
    const float* x   = (const float*)d_in[0];
    const float* Wi  = (const float*)d_in[2];  const float* bWi = (const float*)d_in[3];
    const float* Ui  = (const float*)d_in[4];  const float* bUi = (const float*)d_in[5];
    const float* Wf  = (const float*)d_in[6];  const float* bWf = (const float*)d_in[7];
    const float* Uf  = (const float*)d_in[8];  const float* bUf = (const float*)d_in[9];
    const float* Wo  = (const float*)d_in[10]; const float* bWo = (const float*)d_in[11];
    const float* Uo  = (const float*)d_in[12]; const float* bUo = (const float*)d_in[13];
    const float* Wu  = (const float*)d_in[14]; const float* bWu = (const float*)d_in[15];
    const float* Uu  = (const float*)d_in[16]; const float* bUu = (const float*)d_in[17];
    const float* Wp  = (const float*)d_in[18]; const float* bWp = (const float*)d_in[19];
    float* out = (float*)d_out;

    cudaFuncSetAttribute(gemmIT,      cudaFuncAttributeMaxDynamicSharedMemorySize, IT_SMEM);
    cudaFuncSetAttribute(gemmLV,      cudaFuncAttributeMaxDynamicSharedMemorySize, LV_SMEM);
    cudaFuncSetAttribute(deep_levels, cudaFuncAttributeMaxDynamicSharedMemorySize, DEEP_SMEM);

    prep<<<(4 * H * H + 255) / 256, 256>>>(Wi, Wf, Wo, Wu, Ui, Uo, Uu, Uf,
                                           bWi, bWf, bWo, bWu);
    zero_bar<<<1, 32>>>();

    // 1) merged input transform + fused leaf pointwise
    gemmIT<<<(NN + 127) / 128, 256, IT_SMEM>>>(x);

    // 2) big internal levels, d = 15..DEEP_D+1
    for (int d = DEPTH - 2; d > DEEP_D; --d) {
        const int s   = (1 << d) - 1;
        const int cnt = 1 << d;
        const int cs  = 2 * s + 1;
        gemmLV<<<(2 * cnt) / 128, 256, LV_SMEM>>>(cs, 0);
        node_pw4<<<(cnt * 32 + 255) / 256, 256>>>(s, cnt, bUi, bUo, bUu, bUf);
    }

    // 3) deep levels d = DEEP_D..0
    deep_levels<<<DEEP_BLOCKS, 256, DEEP_SMEM>>>(Ui, Uo, Uu, Uf, bUi, bUo, bUu, bUf);

    // 4) output projection
    final_proj<<<1, H>>>(Wp, bWp, out);
}